// round 3
// baseline (speedup 1.0000x reference)
#include <cuda_runtime.h>

// LengthRegulator scatter: out[b,t,:] = x[b,j,:] for t in token j's interval.
// Row duration sums are exactly T_OUT, so scatter covers the output exactly.

#define BB 32
#define SS 512
#define DD 384
#define T_OUT 2048
#define DV (DD / 4)   // 96 float4 per row
#define TOK 8         // tokens per expand block

// Exclusive-cumsum start offsets per (b, token). Device global (no-alloc rule).
__device__ int g_start[BB * SS];

// Kernel 1: per-batch inclusive scan of durations -> exclusive starts.
__global__ void lr_scan_kernel(const int* __restrict__ dur) {
    __shared__ int s[SS];
    const int b = blockIdx.x;
    const int t = threadIdx.x;
    const int d = dur[b * SS + t];
    s[t] = d;
    __syncthreads();
    #pragma unroll
    for (int off = 1; off < SS; off <<= 1) {
        int v = (t >= off) ? s[t - off] : 0;
        __syncthreads();
        s[t] += v;
        __syncthreads();
    }
    g_start[b * SS + t] = s[t] - d;
}

// Kernel 2: block (g, b) handles TOK consecutive tokens. All 8 x-row loads are
// issued up front (MLP=8); the 8 tokens' frames are contiguous, so the store
// stream is one monotonic coalesced walk.
__global__ void lr_expand_kernel(const float4* __restrict__ x4,
                                 const int* __restrict__ dur,
                                 float4* __restrict__ out4) {
    const int g = blockIdx.x;            // token group 0..63
    const int b = blockIdx.y;
    const int c = threadIdx.x;           // 0..95
    const int j0 = g * TOK;
    const int idx0 = b * SS + j0;

    // 8 independent row loads — deep MLP, one latency exposure.
    float4 v[TOK];
    #pragma unroll
    for (int i = 0; i < TOK; ++i)
        v[i] = __ldg(&x4[(size_t)(idx0 + i) * DV + c]);

    // Durations: two vectorized loads (idx0 is 8-int aligned).
    const int4* d4 = (const int4*)(dur + idx0);
    const int4 da = __ldg(&d4[0]);
    const int4 db = __ldg(&d4[1]);
    int durs[TOK] = {da.x, da.y, da.z, da.w, db.x, db.y, db.z, db.w};

    const int start = g_start[idx0];     // group base; rest follow by prefix

    float4* o = out4 + ((size_t)b * T_OUT + start) * DV + c;
    #pragma unroll
    for (int i = 0; i < TOK; ++i) {
        for (int k = 0; k < durs[i]; ++k) {
            __stcs(o, v[i]);             // streaming: output never re-read
            o += DV;
        }
    }
}

extern "C" void kernel_launch(void* const* d_in, const int* in_sizes, int n_in,
                              void* d_out, int out_size) {
    const float4* x4  = (const float4*)d_in[0];   // x [B,S,D] f32
    const int*    dur = (const int*)d_in[1];      // durations [B,S] i32
    float4* out4 = (float4*)d_out;                // [B,T_OUT,D] f32

    lr_scan_kernel<<<BB, SS>>>(dur);
    lr_expand_kernel<<<dim3(SS / TOK, BB), DV>>>(x4, dur, out4);
}

// round 6
// speedup vs baseline: 1.0056x; 1.0056x over previous
#include <cuda_runtime.h>

// LengthRegulator as a dense gather:
//   kernel 1: scan durations -> frame->token index table g_idx[B][T_OUT]
//   kernel 2: out[b,t,:] = x[b, g_idx[b,t], :]   (flat streaming copy)

#define BB 32
#define SS 512
#define DD 384
#define T_OUT 2048
#define DV (DD / 4)   // 96 float4 per row
#define FR 16         // frames per expand block
#define FL 4          // frame lanes; block = DV * FL = 384 threads (12 warps)

// frame -> token index table (no-alloc rule: device global scratch)
__device__ int g_idx[BB * T_OUT];

// Kernel 1: per-batch scan of durations, then scatter token ids into g_idx.
__global__ void lr_scan_kernel(const int* __restrict__ dur) {
    __shared__ int s[SS];
    const int b = blockIdx.x;
    const int t = threadIdx.x;
    const int d = dur[b * SS + t];
    s[t] = d;
    __syncthreads();
    #pragma unroll
    for (int off = 1; off < SS; off <<= 1) {
        int v = (t >= off) ? s[t - off] : 0;
        __syncthreads();
        s[t] += v;
        __syncthreads();
    }
    int start = s[t] - d;                 // exclusive prefix
    int* row = g_idx + b * T_OUT;
    for (int k = 0; k < d; ++k) {
        int p = start + k;
        if (p < T_OUT) row[p] = t;        // defensive bound; sums == T_OUT
    }
}

// Kernel 2: block (fg, b) produces FR=16 contiguous output frames.
// 384 threads: threadIdx.x = channel (0..95 float4), threadIdx.y = frame lane.
// Each thread: 4 index loads (broadcast, L1-resident) + 4 independent row
// gathers batched before 4 streaming stores into a dense monotonic span.
// No divergence, no barrier, all 4 SMSPs busy.
__global__ void lr_expand_kernel(const float4* __restrict__ x4,
                                 float4* __restrict__ out4) {
    const int b  = blockIdx.y;
    const int t0 = blockIdx.x * FR;
    const int c  = threadIdx.x;           // 0..95
    const int f  = threadIdx.y;           // 0..3

    const int* __restrict__ idx = g_idx + b * T_OUT + t0;
    const float4* __restrict__ xb = x4 + (size_t)b * SS * DV + c;
    float4* __restrict__ ob = out4 + ((size_t)b * T_OUT + t0 + f) * DV + c;

    // gather frames t0 + f + 4*i, i = 0..3 (independent -> MLP=4 per thread)
    int tok[FR / FL];
    #pragma unroll
    for (int i = 0; i < FR / FL; ++i) {
        int tk = __ldg(&idx[f + FL * i]);
        tok[i] = min(tk, SS - 1);         // defensive clamp (free on ALU pipe)
    }

    float4 v[FR / FL];
    #pragma unroll
    for (int i = 0; i < FR / FL; ++i)
        v[i] = __ldg(&xb[(size_t)tok[i] * DV]);

    // streaming stores: output never re-read; keep x resident in L2
    #pragma unroll
    for (int i = 0; i < FR / FL; ++i)
        __stcs(&ob[(size_t)(FL * i) * DV], v[i]);
}

extern "C" void kernel_launch(void* const* d_in, const int* in_sizes, int n_in,
                              void* d_out, int out_size) {
    const float4* x4  = (const float4*)d_in[0];   // x [B,S,D] f32
    const int*    dur = (const int*)d_in[1];      // durations [B,S] i32
    float4* out4 = (float4*)d_out;                // [B,T_OUT,D] f32

    lr_scan_kernel<<<BB, SS>>>(dur);
    lr_expand_kernel<<<dim3(T_OUT / FR, BB), dim3(DV, FL)>>>(x4, out4);
}

// round 8
// speedup vs baseline: 1.0169x; 1.0113x over previous
#include <cuda_runtime.h>

// LengthRegulator, single fused kernel:
// each block scans its batch's durations in smem (redundant per block, L2-hit),
// scatters its 64-frame window's frame->token map, then does the dense
// gather + streaming-store copy. One graph node, no intermediate table.

#define BB 32
#define SS 512
#define DD 384
#define T_OUT 2048
#define DV (DD / 4)     // 96 float4 per row
#define FRB 64          // frames per block
#define NT 384          // threads per block (12 warps, all SMSPs)
#define FL 4            // frame lanes (NT / DV)

__global__ __launch_bounds__(NT)
void lr_fused_kernel(const float4* __restrict__ x4,
                     const int* __restrict__ dur,
                     float4* __restrict__ out4) {
    __shared__ int sa[SS], sb[SS];     // ping-pong scan buffers
    __shared__ int sidx[FRB];          // frame -> token for this window

    const int b   = blockIdx.y;
    const int t0  = blockIdx.x * FRB;
    const int tid = threadIdx.x;

    // 1) load durations for this batch (2KB, L2-resident after first touch)
    for (int p = tid; p < SS; p += NT)
        sa[p] = __ldg(&dur[b * SS + p]);
    __syncthreads();

    // 2) inclusive Hillis-Steele scan, ping-pong (no RAW hazards)
    int* src = sa;
    int* dst = sb;
    #pragma unroll
    for (int off = 1; off < SS; off <<= 1) {
        #pragma unroll 2
        for (int p = tid; p < SS; p += NT)
            dst[p] = src[p] + (p >= off ? src[p - off] : 0);
        __syncthreads();
        int* tmp = src; src = dst; dst = tmp;
    }

    // 3) scatter this window's frame->token indices
    //    (each thread handles 1-2 tokens; interval clipped to [t0, t0+FRB))
    for (int p = tid; p < SS; p += NT) {
        const int s = p ? src[p - 1] : 0;      // exclusive prefix
        const int e = src[p];                  // inclusive prefix
        int lo = s > t0 ? s : t0;
        int hi = e < t0 + FRB ? e : t0 + FRB;
        for (int k = lo; k < hi; ++k)
            sidx[k - t0] = p;
    }
    __syncthreads();

    // 4) copy: c = channel (0..95 float4), f = frame lane (0..3).
    //    Lane f covers frames t0 + f + 4*i, batched 4-wide for MLP.
    const int c = tid % DV;                    // contiguous within warp
    const int f = tid / DV;
    const float4* __restrict__ xb = x4 + (size_t)b * SS * DV + c;
    float4* __restrict__ ob = out4 + ((size_t)b * T_OUT + t0) * DV + c;

    #pragma unroll
    for (int g = 0; g < FRB / FL; g += 4) {
        int tk[4];
        #pragma unroll
        for (int i = 0; i < 4; ++i)
            tk[i] = sidx[f + FL * (g + i)];

        float4 v[4];
        #pragma unroll
        for (int i = 0; i < 4; ++i)
            v[i] = __ldg(&xb[(size_t)tk[i] * DV]);

        #pragma unroll
        for (int i = 0; i < 4; ++i)
            __stcs(&ob[(size_t)(f + FL * (g + i)) * DV], v[i]);
    }
}

extern "C" void kernel_launch(void* const* d_in, const int* in_sizes, int n_in,
                              void* d_out, int out_size) {
    const float4* x4  = (const float4*)d_in[0];   // x [B,S,D] f32
    const int*    dur = (const int*)d_in[1];      // durations [B,S] i32
    float4* out4 = (float4*)d_out;                // [B,T_OUT,D] f32

    lr_fused_kernel<<<dim3(T_OUT / FRB, BB), NT>>>(x4, dur, out4);
}